// round 14
// baseline (speedup 1.0000x reference)
#include <cuda_runtime.h>
#include <cuda_bf16.h>
#include <cuda_fp16.h>
#include <cstdint>

#define LEAKY 0.01f

static constexpr int MAX_N = 100000;
static constexpr int MAX_E = 1600000;

// Scratch (module-scope device globals; allocation inside kernel_launch is forbidden)
__device__ __half   g_h16[(size_t)MAX_N * 128];  // GEMM output buffer A
__device__ __half   g_h16b[(size_t)MAX_N * 64];  // GEMM output buffer B (layer-1, 64 cols)
__device__ float    g_agg[(size_t)MAX_N * 128];  // gather destination (fp32)
__device__ float    g_rs_out[MAX_N];             // rsqrt(max(out_deg,1))
__device__ float    g_rs_in[MAX_N];              // rsqrt(max(in_deg,1))
__device__ int      g_indeg[MAX_N];              // int in-degree counts
__device__ int      g_excl[MAX_N];               // scan scratch
__device__ int      g_row_start[MAX_N + 1];      // CSR row offsets (by dst)
__device__ int      g_cursor[MAX_N];             // CSR fill cursors
__device__ int      g_csr_src[MAX_E];            // CSR column (src node) array
__device__ int      g_bsum[512];                 // scan block sums
__device__ uint32_t g_bth0[128 * 64];            // W0^T fp16-hi half2 [n][k/2]
__device__ uint32_t g_bth1[64 * 64];             // W1^T
__device__ uint32_t g_bth2[64 * 32];             // W2^T

__device__ __forceinline__ float lrelu(float t) {
    return (t >= 0.f) ? t : LEAKY * t;
}

__device__ __forceinline__ uint32_t h2bits(__half2 h) {
    return *reinterpret_cast<uint32_t*>(&h);
}

// split two floats into fp16 hi/lo planes packed as half2 words
__device__ __forceinline__ uint2 split2(float a, float b) {
    __half2 h = __floats2half2_rn(a, b);
    float la = a - __low2float(h);
    float lb = b - __high2float(h);
    __half2 l = __floats2half2_rn(la, lb);
    return make_uint2(h2bits(h), h2bits(l));
}

__device__ __forceinline__ void mma_f16(float* d, const uint32_t* a, const uint32_t* b) {
    asm volatile(
        "mma.sync.aligned.m16n8k16.row.col.f32.f16.f16.f32 "
        "{%0,%1,%2,%3}, {%4,%5,%6,%7}, {%8,%9}, {%0,%1,%2,%3};"
        : "+f"(d[0]), "+f"(d[1]), "+f"(d[2]), "+f"(d[3])
        : "r"(a[0]), "r"(a[1]), "r"(a[2]), "r"(a[3]), "r"(b[0]), "r"(b[1]));
}

__device__ __forceinline__ uint32_t cvta_smem(const void* p) {
    uint32_t a;
    asm("{ .reg .u64 t; cvta.to.shared.u64 t, %1; cvt.u32.u64 %0, t; }" : "=r"(a) : "l"(p));
    return a;
}

__device__ __forceinline__ void ldsm_x4(uint32_t* r, uint32_t addr) {
    asm volatile("ldmatrix.sync.aligned.m8n8.x4.shared.b16 {%0,%1,%2,%3}, [%4];"
                 : "=r"(r[0]), "=r"(r[1]), "=r"(r[2]), "=r"(r[3]) : "r"(addr));
}

__device__ __forceinline__ void ldsm_x2(uint32_t* r, uint32_t addr) {
    asm volatile("ldmatrix.sync.aligned.m8n8.x2.shared.b16 {%0,%1}, [%2];"
                 : "=r"(r[0]), "=r"(r[1]) : "r"(addr));
}

// ---------------------------------------------------------------------------
// Degrees: single E pass, both atomics
// ---------------------------------------------------------------------------
__global__ void deg_kernel(const int* __restrict__ src, const int* __restrict__ dst,
                           float* __restrict__ dout, int* __restrict__ indeg, int E) {
    int i = blockIdx.x * blockDim.x + threadIdx.x;
    if (i < E) {
        atomicAdd(&dout[src[i]], 1.0f);
        atomicAdd(&indeg[dst[i]], 1);
    }
}

__global__ void rsqrt_kernel(float* __restrict__ dout, const int* __restrict__ indeg,
                             float* __restrict__ rsin, int N) {
    int i = blockIdx.x * blockDim.x + threadIdx.x;
    if (i < N) {
        dout[i] = rsqrtf(fmaxf(dout[i], 1.0f));
        rsin[i] = rsqrtf(fmaxf((float)indeg[i], 1.0f));
    }
}

// ---------------------------------------------------------------------------
// Exclusive scan over in-degrees
// ---------------------------------------------------------------------------
__global__ void scan_block(const int* __restrict__ deg, int* __restrict__ excl,
                           int* __restrict__ bsum, int N) {
    __shared__ int ts[256];
    int tid = threadIdx.x;
    int base = blockIdx.x * 1024 + tid * 4;
    int v[4];
    int sum = 0;
#pragma unroll
    for (int i = 0; i < 4; i++) {
        int idx = base + i;
        v[i] = (idx < N) ? deg[idx] : 0;
        sum += v[i];
    }
    ts[tid] = sum;
    __syncthreads();
    for (int off = 1; off < 256; off <<= 1) {
        int t = (tid >= off) ? ts[tid - off] : 0;
        __syncthreads();
        ts[tid] += t;
        __syncthreads();
    }
    if (tid == 255) bsum[blockIdx.x] = ts[255];
    int run = ts[tid] - sum;
#pragma unroll
    for (int i = 0; i < 4; i++) {
        int idx = base + i;
        if (idx < N) excl[idx] = run;
        run += v[i];
    }
}

__global__ void scan_bsum(int* __restrict__ bsum, int nb) {
    __shared__ int s[512];
    int tid = threadIdx.x;
    int v = (tid < nb) ? bsum[tid] : 0;
    s[tid] = v;
    __syncthreads();
    for (int off = 1; off < 512; off <<= 1) {
        int t = (tid >= off) ? s[tid - off] : 0;
        __syncthreads();
        s[tid] += t;
        __syncthreads();
    }
    if (tid < nb) bsum[tid] = s[tid] - v;
}

__global__ void scan_add(const int* __restrict__ excl, const int* __restrict__ bsum,
                         int* __restrict__ row_start, int* __restrict__ cursor,
                         int N, int E) {
    int i = blockIdx.x * blockDim.x + threadIdx.x;
    if (i < N) {
        int v = excl[i] + bsum[i >> 10];
        row_start[i] = v;
        cursor[i] = v;
    }
    if (i == 0) row_start[N] = E;
}

__global__ void fill_csr(const int* __restrict__ src, const int* __restrict__ dst,
                         int* __restrict__ cursor, int* __restrict__ csr_src, int E) {
    int e = blockIdx.x * blockDim.x + threadIdx.x;
    if (e < E) {
        int pos = atomicAdd(&cursor[dst[e]], 1);
        csr_src[pos] = src[e];
    }
}

// ---------------------------------------------------------------------------
// All three W transposes+fp16 conversions in one launch
// ---------------------------------------------------------------------------
__global__ void split_w_all(const float* __restrict__ W0, const float* __restrict__ W1,
                            const float* __restrict__ W2, uint32_t* __restrict__ o0,
                            uint32_t* __restrict__ o1, uint32_t* __restrict__ o2) {
    int idx = blockIdx.x * blockDim.x + threadIdx.x;
    if (idx < 8192) {
        const int KP = 64, BN = 128;
        int n = idx / KP, j = idx % KP;
        o0[idx] = h2bits(__floats2half2_rn(W0[(size_t)(2 * j) * BN + n],
                                           W0[(size_t)(2 * j + 1) * BN + n]));
    } else if (idx < 12288) {
        int i = idx - 8192;
        const int KP = 64, BN = 64;
        int n = i / KP, j = i % KP;
        o1[i] = h2bits(__floats2half2_rn(W1[(size_t)(2 * j) * BN + n],
                                         W1[(size_t)(2 * j + 1) * BN + n]));
    } else if (idx < 14336) {
        int i = idx - 12288;
        const int KP = 32, BN = 64;
        int n = i / KP, j = i % KP;
        o2[i] = h2bits(__floats2half2_rn(W2[(size_t)(2 * j) * BN + n],
                                         W2[(size_t)(2 * j + 1) * BN + n]));
    }
}

// ---------------------------------------------------------------------------
// fp16 2-term split GEMM (m16n8k16) with ldmatrix fragment loads.
// Processes rows [row0, nrows) in blocks of 128 (grid sized by caller).
// ---------------------------------------------------------------------------
template<int K, int BN, bool FIRST>
__global__ __launch_bounds__(256, 2)
void gemm_mma(const float* __restrict__ A, const uint32_t* __restrict__ Bt,
              const float* __restrict__ bprev,
              const float* __restrict__ rs_out, const float* __restrict__ rs_in,
              __half* __restrict__ outh, int nrows, int row0)
{
    constexpr int WARPS_M = (BN == 128) ? 2 : 4;
    constexpr int WM = 128 / WARPS_M;   // 64 or 32
    constexpr int WN = 32;
    constexpr int MF = WM / 16;         // 4 or 2
    constexpr int NF = 4;
    constexpr int KP = K / 2;
    constexpr int AS32 = 20;            // uint32 per A-plane row (32 halves + 8 pad)
    constexpr int APLANE = 128 * AS32;  // uint32 per plane
    constexpr int BS32 = KP + 4;        // uint32 per B row
    constexpr int NCHUNK = K / 32;

    extern __shared__ __align__(16) uint32_t smw[];
    // [Ahi0][Alo0][Ahi1][Alo1][Bs]
    uint32_t* Bs = smw + 4 * APLANE;

    const int tid = threadIdx.x;
    const int wid = tid >> 5;
    const int lane = tid & 31;
    const int wm = wid % WARPS_M;
    const int wn = wid / WARPS_M;
    const int rowBase = row0 + blockIdx.x * 128;
    const int g = lane >> 2;
    const int t4 = lane & 3;

    // ---- load resident B (hi plane only) ----
    constexpr int BU4 = BN * KP / 4;
#pragma unroll 4
    for (int idx = tid; idx < BU4; idx += 256) {
        int lin = idx * 4;
        int n = lin / KP;
        int j = lin % KP;
        uint4 v = *(const uint4*)(Bt + (size_t)n * KP + j);
        *(uint4*)(Bs + n * BS32 + j) = v;
    }

    // ---- A chunk staging: thread covers row a_r, 16 consecutive k ----
    const int a_r = tid >> 1;
    const int a_kh = tid & 1;  // which 16-k half of the 32-k chunk
    float4 q[4];

    auto load_a = [&](int c) {
        int row = rowBase + a_r;
        int kb = c * 32 + a_kh * 16;
        if (row < nrows) {
            const float* ap = A + (size_t)row * K + kb;
#pragma unroll
            for (int i = 0; i < 4; i++) q[i] = *(const float4*)(ap + i * 4);
            if (FIRST) {
                float ro = rs_out[row];
#pragma unroll
                for (int i = 0; i < 4; i++) {
                    q[i].x *= ro; q[i].y *= ro; q[i].z *= ro; q[i].w *= ro;
                }
            } else {
                float ri = rs_in[row];
                float ro = rs_out[row];
#pragma unroll
                for (int i = 0; i < 4; i++) {
                    int kk = kb + i * 4;
                    q[i].x = lrelu(fmaf(q[i].x, ri, bprev[kk + 0])) * ro;
                    q[i].y = lrelu(fmaf(q[i].y, ri, bprev[kk + 1])) * ro;
                    q[i].z = lrelu(fmaf(q[i].z, ri, bprev[kk + 2])) * ro;
                    q[i].w = lrelu(fmaf(q[i].w, ri, bprev[kk + 3])) * ro;
                }
            }
        } else {
#pragma unroll
            for (int i = 0; i < 4; i++) q[i] = make_float4(0.f, 0.f, 0.f, 0.f);
        }
    };
    auto sts_a = [&](int parity) {
        uint32_t* H = smw + parity * 2 * APLANE;
        uint32_t* L = H + APLANE;
#pragma unroll
        for (int h = 0; h < 2; h++) {
            uint2 e0 = split2(q[2 * h].x,     q[2 * h].y);
            uint2 e1 = split2(q[2 * h].z,     q[2 * h].w);
            uint2 e2 = split2(q[2 * h + 1].x, q[2 * h + 1].y);
            uint2 e3 = split2(q[2 * h + 1].z, q[2 * h + 1].w);
            int off = a_r * AS32 + a_kh * 8 + h * 4;
            *(uint4*)(H + off) = make_uint4(e0.x, e1.x, e2.x, e3.x);
            *(uint4*)(L + off) = make_uint4(e0.y, e1.y, e2.y, e3.y);
        }
    };

    const uint32_t smw_base = cvta_smem(smw);
    const uint32_t a_lane_off = (uint32_t)(lane & 15) * (AS32 * 4) + ((lane >> 4) << 4);
    const uint32_t b_base = cvta_smem(Bs);
    const uint32_t b_lane_off = (uint32_t)(lane & 7) * (BS32 * 4) + (((lane >> 3) & 1) << 4);

    load_a(0);
    sts_a(0);
    __syncthreads();

    float acc[MF][NF][4];
#pragma unroll
    for (int i = 0; i < MF; i++)
#pragma unroll
        for (int j = 0; j < NF; j++)
#pragma unroll
            for (int c = 0; c < 4; c++) acc[i][j][c] = 0.f;

#pragma unroll
    for (int c = 0; c < NCHUNK; c++) {
        const uint32_t ahi_base = smw_base + (uint32_t)(c & 1) * (2 * APLANE * 4);
        const uint32_t alo_base = ahi_base + APLANE * 4;
        if (c + 1 < NCHUNK) load_a(c + 1);  // LDG overlaps compute

#pragma unroll
        for (int ks = 0; ks < 2; ks++) {
            const uint32_t akoff = (uint32_t)(ks * 16) * 2;
            uint32_t ah[MF][4], al[MF][4];
#pragma unroll
            for (int mf = 0; mf < MF; mf++) {
                uint32_t rowoff = (uint32_t)(wm * WM + mf * 16) * (AS32 * 4);
                ldsm_x4(ah[mf], ahi_base + rowoff + akoff + a_lane_off);
                ldsm_x4(al[mf], alo_base + rowoff + akoff + a_lane_off);
            }
            uint32_t bh[NF][2];
            const uint32_t bkoff = (uint32_t)(c * 32 + ks * 16) * 2;
#pragma unroll
            for (int nf = 0; nf < NF; nf++) {
                uint32_t noff = (uint32_t)(wn * WN + nf * 8) * (BS32 * 4);
                ldsm_x2(bh[nf], b_base + noff + bkoff + b_lane_off);
            }
#pragma unroll
            for (int mf = 0; mf < MF; mf++)
#pragma unroll
                for (int nf = 0; nf < NF; nf++) {
                    mma_f16(acc[mf][nf], ah[mf], bh[nf]);
                    mma_f16(acc[mf][nf], al[mf], bh[nf]);
                }
        }
        if (c + 1 < NCHUNK) {
            sts_a((c + 1) & 1);
            __syncthreads();
        }
    }

    // ---- store h as fp16 ----
#pragma unroll
    for (int mf = 0; mf < MF; mf++) {
#pragma unroll
        for (int nf = 0; nf < NF; nf++) {
            int r0 = rowBase + wm * WM + mf * 16 + g;
            int col = wn * WN + nf * 8 + t4 * 2;
            if (r0 < nrows)
                *(__half2*)(outh + (size_t)r0 * BN + col) =
                    __floats2half2_rn(acc[mf][nf][0], acc[mf][nf][1]);
            if (r0 + 8 < nrows)
                *(__half2*)(outh + (size_t)(r0 + 8) * BN + col) =
                    __floats2half2_rn(acc[mf][nf][2], acc[mf][nf][3]);
        }
    }
}

// ---------------------------------------------------------------------------
// CSR gather aggregation from fp16 h (fp32 accumulate), nodes [node0, nodeEnd)
// ---------------------------------------------------------------------------
__global__ __launch_bounds__(256)
void gather128(const int* __restrict__ row_start, const int* __restrict__ csr,
               const __half* __restrict__ h, float* __restrict__ agg,
               int node0, int nodeEnd)
{
    int warp = node0 + ((blockIdx.x * blockDim.x + threadIdx.x) >> 5);
    int lane = threadIdx.x & 31;
    if (warp >= nodeEnd) return;
    int start = row_start[warp];
    int end   = row_start[warp + 1];
    float4 acc = make_float4(0.f, 0.f, 0.f, 0.f);
    for (int j = start; j < end; j++) {
        int s0 = __ldg(&csr[j]);
        uint2 raw = *(const uint2*)(h + (size_t)s0 * 128 + lane * 4);
        float2 fa = __half22float2(*(__half2*)&raw.x);
        float2 fb = __half22float2(*(__half2*)&raw.y);
        acc.x += fa.x; acc.y += fa.y; acc.z += fb.x; acc.w += fb.y;
    }
    *(float4*)(agg + (size_t)warp * 128 + lane * 4) = acc;
}

__global__ __launch_bounds__(256)
void gather64(const int* __restrict__ row_start, const int* __restrict__ csr,
              const __half* __restrict__ h, float* __restrict__ agg,
              int node0, int nodeEnd)
{
    int warp = node0 + ((blockIdx.x * blockDim.x + threadIdx.x) >> 5);
    int lane = threadIdx.x & 31;
    if (warp >= nodeEnd) return;
    int start = row_start[warp];
    int end   = row_start[warp + 1];
    float2 acc = make_float2(0.f, 0.f);
    for (int j = start; j < end; j++) {
        int s0 = __ldg(&csr[j]);
        __half2 raw = *(const __half2*)(h + (size_t)s0 * 64 + lane * 2);
        float2 f = __half22float2(raw);
        acc.x += f.x; acc.y += f.y;
    }
    *(float2*)(agg + (size_t)warp * 64 + lane * 2) = acc;
}

// Final-layer gather with fused epilogue: out = lrelu(acc * rs_in + b2)
__global__ __launch_bounds__(256)
void gather64_epi(const int* __restrict__ row_start, const int* __restrict__ csr,
                  const __half* __restrict__ h, const float* __restrict__ rs_in,
                  const float* __restrict__ b, float* __restrict__ out, int N)
{
    int warp = (blockIdx.x * blockDim.x + threadIdx.x) >> 5;
    int lane = threadIdx.x & 31;
    if (warp >= N) return;
    int start = row_start[warp];
    int end   = row_start[warp + 1];
    float2 acc = make_float2(0.f, 0.f);
    for (int j = start; j < end; j++) {
        int s0 = __ldg(&csr[j]);
        __half2 raw = *(const __half2*)(h + (size_t)s0 * 64 + lane * 2);
        float2 f = __half22float2(raw);
        acc.x += f.x; acc.y += f.y;
    }
    float ri = rs_in[warp];
    int c = lane * 2;
    float2 o;
    o.x = lrelu(fmaf(acc.x, ri, b[c + 0]));
    o.y = lrelu(fmaf(acc.y, ri, b[c + 1]));
    *(float2*)(out + (size_t)warp * 64 + c) = o;
}

// ---------------------------------------------------------------------------
// Launch
// ---------------------------------------------------------------------------
static inline int cdiv(int a, int b) { return (a + b - 1) / b; }

extern "C" void kernel_launch(void* const* d_in, const int* in_sizes, int n_in,
                              void* d_out, int out_size)
{
    const float* n_feat = (const float*)d_in[0];
    const int*   src    = (const int*)  d_in[1];
    const int*   dst    = (const int*)  d_in[2];
    const float* W0     = (const float*)d_in[3];
    const float* b0     = (const float*)d_in[4];
    const float* W1     = (const float*)d_in[5];
    const float* b1     = (const float*)d_in[6];
    const float* W2     = (const float*)d_in[7];
    const float* b2     = (const float*)d_in[8];
    float* out = (float*)d_out;

    const int N = in_sizes[0] / 128;
    const int E = in_sizes[1];

    float *d_agg, *d_rso, *d_rsi;
    __half *d_ha, *d_hb;
    int *d_indeg, *d_excl, *d_rs, *d_cur, *d_csr, *d_bsum;
    uint32_t *d_bth0, *d_bth1, *d_bth2;
    cudaGetSymbolAddress((void**)&d_ha,   g_h16);
    cudaGetSymbolAddress((void**)&d_hb,   g_h16b);
    cudaGetSymbolAddress((void**)&d_agg,  g_agg);
    cudaGetSymbolAddress((void**)&d_rso,  g_rs_out);
    cudaGetSymbolAddress((void**)&d_rsi,  g_rs_in);
    cudaGetSymbolAddress((void**)&d_indeg, g_indeg);
    cudaGetSymbolAddress((void**)&d_excl, g_excl);
    cudaGetSymbolAddress((void**)&d_rs,   g_row_start);
    cudaGetSymbolAddress((void**)&d_cur,  g_cursor);
    cudaGetSymbolAddress((void**)&d_csr,  g_csr_src);
    cudaGetSymbolAddress((void**)&d_bsum, g_bsum);
    cudaGetSymbolAddress((void**)&d_bth0, g_bth0);
    cudaGetSymbolAddress((void**)&d_bth1, g_bth1);
    cudaGetSymbolAddress((void**)&d_bth2, g_bth2);

    constexpr int SMEM_L0 = 4 * 128 * 20 * 4 + 128 * 68 * 4;  // 75776
    constexpr int SMEM_L1 = 4 * 128 * 20 * 4 + 64 * 68 * 4;   // 58368
    constexpr int SMEM_L2 = 4 * 128 * 20 * 4 + 64 * 36 * 4;   // 50176

    static cudaStream_t s2 = nullptr;
    static cudaEvent_t ev0 = nullptr, ev1 = nullptr;
    static cudaEvent_t eA[4], eC[4], eB1 = nullptr, eB2 = nullptr;
    if (!s2) {
        cudaFuncSetAttribute(gemm_mma<128, 128, true>,
                             cudaFuncAttributeMaxDynamicSharedMemorySize, SMEM_L0);
        cudaFuncSetAttribute(gemm_mma<128, 64, false>,
                             cudaFuncAttributeMaxDynamicSharedMemorySize, SMEM_L1);
        cudaFuncSetAttribute(gemm_mma<64, 64, false>,
                             cudaFuncAttributeMaxDynamicSharedMemorySize, SMEM_L2);
        cudaStreamCreateWithFlags(&s2, cudaStreamNonBlocking);
        cudaEventCreateWithFlags(&ev0, cudaEventDisableTiming);
        cudaEventCreateWithFlags(&ev1, cudaEventDisableTiming);
        for (int i = 0; i < 4; i++) {
            cudaEventCreateWithFlags(&eA[i], cudaEventDisableTiming);
            cudaEventCreateWithFlags(&eC[i], cudaEventDisableTiming);
        }
        cudaEventCreateWithFlags(&eB1, cudaEventDisableTiming);
        cudaEventCreateWithFlags(&eB2, cudaEventDisableTiming);
    }

    const int gemm_blocks = cdiv(N, 128);
    const int nb = cdiv(N, 1024);
    const int QN = 25088;  // quarter span, multiple of 128

    // ---- main stream head (launches 1-6; #6 = gemm0 for ncu -s 5) ----
    cudaMemsetAsync(d_indeg, 0, (size_t)N * sizeof(int));                      // 1
    cudaMemsetAsync(d_rso, 0, (size_t)N * sizeof(float));                      // 2
    deg_kernel<<<cdiv(E, 256), 256>>>(src, dst, d_rso, d_indeg, E);            // 3
    cudaEventRecord(ev0, 0);  // fork point: indeg ready
    rsqrt_kernel<<<cdiv(N, 256), 256>>>(d_rso, d_indeg, d_rsi, N);             // 4
    split_w_all<<<cdiv(14336, 256), 256>>>(W0, W1, W2, d_bth0, d_bth1, d_bth2);// 5
    gemm_mma<128, 128, true><<<gemm_blocks, 256, SMEM_L0>>>(                   // 6
        n_feat, d_bth0, nullptr, d_rso, d_rsi, d_ha, N, 0);

    // ---- s2: CSR chain, concurrent with rsqrt/split_w/gemm0 ----
    cudaStreamWaitEvent(s2, ev0, 0);
    scan_block<<<nb, 256, 0, s2>>>(d_indeg, d_excl, d_bsum, N);
    scan_bsum<<<1, 512, 0, s2>>>(d_bsum, nb);
    scan_add<<<cdiv(N, 256), 256, 0, s2>>>(d_excl, d_bsum, d_rs, d_cur, N, E);
    fill_csr<<<cdiv(E, 256), 256, 0, s2>>>(src, dst, d_cur, d_csr, E);
    cudaEventRecord(ev1, s2);

    // ---- join: gathers need the CSR ----
    cudaStreamWaitEvent(0, ev1, 0);

    // ---- pipelined: gather128 reads h_a (main) / gemm1 writes h_b (s2) ----
    for (int q = 0; q < 4; q++) {
        int n0 = q * QN;
        int n1 = (q == 3) ? N : (q + 1) * QN;
        gather128<<<cdiv(n1 - n0, 8), 256>>>(d_rs, d_csr, d_ha, d_agg, n0, n1);
        cudaEventRecord(eA[q], 0);
    }
    for (int q = 0; q < 4; q++) {
        int n0 = q * QN;
        int n1 = (q == 3) ? N : (q + 1) * QN;
        cudaStreamWaitEvent(s2, eA[q], 0);
        gemm_mma<128, 64, false><<<cdiv(n1 - n0, 128), 256, SMEM_L1, s2>>>(
            d_agg, d_bth1, b0, d_rso, d_rsi, d_hb, n1, n0);
    }
    cudaEventRecord(eB1, s2);

    // ---- pipelined: gather64 reads h_b (main) / gemm2 writes h_a (s2) ----
    cudaStreamWaitEvent(0, eB1, 0);
    for (int q = 0; q < 4; q++) {
        int n0 = q * QN;
        int n1 = (q == 3) ? N : (q + 1) * QN;
        gather64<<<cdiv(n1 - n0, 8), 256>>>(d_rs, d_csr, d_hb, d_agg, n0, n1);
        cudaEventRecord(eC[q], 0);
    }
    for (int q = 0; q < 4; q++) {
        int n0 = q * QN;
        int n1 = (q == 3) ? N : (q + 1) * QN;
        cudaStreamWaitEvent(s2, eC[q], 0);
        gemm_mma<64, 64, false><<<cdiv(n1 - n0, 128), 256, SMEM_L2, s2>>>(
            d_agg, d_bth2, b1, d_rso, d_rsi, d_ha, n1, n0);
    }
    cudaEventRecord(eB2, s2);

    // ---- final epilogue gather reads h_a (needs all of gemm2) ----
    cudaStreamWaitEvent(0, eB2, 0);
    gather64_epi<<<cdiv(N, 8), 256>>>(d_rs, d_csr, d_ha, d_rsi, b2, out, N);
}

// round 15
// speedup vs baseline: 1.1042x; 1.1042x over previous
#include <cuda_runtime.h>
#include <cuda_bf16.h>
#include <cuda_fp16.h>
#include <cstdint>

#define LEAKY 0.01f

static constexpr int MAX_N = 100000;
static constexpr int MAX_E = 1600000;

// Scratch (module-scope device globals; allocation inside kernel_launch is forbidden)
__device__ __half   g_h16[(size_t)MAX_N * 128];  // GEMM output (fp16) / gather source
__device__ float    g_agg[(size_t)MAX_N * 128];  // gather output (pre-split uint2 view)
__device__ float    g_rs_out[MAX_N];             // rsqrt(max(out_deg,1))
__device__ float    g_rs_in[MAX_N];              // rsqrt(max(in_deg,1))
__device__ int      g_indeg[MAX_N];              // int in-degree counts
__device__ int      g_excl[MAX_N];               // scan scratch
__device__ int      g_row_start[MAX_N + 1];      // CSR row offsets (by dst)
__device__ int      g_cursor[MAX_N];             // CSR fill cursors
__device__ int      g_csr_src[MAX_E];            // CSR column (src node) array
__device__ int      g_bsum[512];                 // scan block sums
__device__ uint32_t g_bth0[128 * 64];            // W0^T fp16-hi half2 [n][k/2]
__device__ uint32_t g_bth1[64 * 64];             // W1^T
__device__ uint32_t g_bth2[64 * 32];             // W2^T

__device__ __forceinline__ float lrelu(float t) {
    return (t >= 0.f) ? t : LEAKY * t;
}

__device__ __forceinline__ uint32_t h2bits(__half2 h) {
    return *reinterpret_cast<uint32_t*>(&h);
}

// split two floats into fp16 hi/lo planes packed as half2 words
__device__ __forceinline__ uint2 split2(float a, float b) {
    __half2 h = __floats2half2_rn(a, b);
    float la = a - __low2float(h);
    float lb = b - __high2float(h);
    __half2 l = __floats2half2_rn(la, lb);
    return make_uint2(h2bits(h), h2bits(l));
}

__device__ __forceinline__ void mma_f16(float* d, const uint32_t* a, const uint32_t* b) {
    asm volatile(
        "mma.sync.aligned.m16n8k16.row.col.f32.f16.f16.f32 "
        "{%0,%1,%2,%3}, {%4,%5,%6,%7}, {%8,%9}, {%0,%1,%2,%3};"
        : "+f"(d[0]), "+f"(d[1]), "+f"(d[2]), "+f"(d[3])
        : "r"(a[0]), "r"(a[1]), "r"(a[2]), "r"(a[3]), "r"(b[0]), "r"(b[1]));
}

__device__ __forceinline__ uint32_t cvta_smem(const void* p) {
    uint32_t a;
    asm("{ .reg .u64 t; cvta.to.shared.u64 t, %1; cvt.u32.u64 %0, t; }" : "=r"(a) : "l"(p));
    return a;
}

__device__ __forceinline__ void ldsm_x4(uint32_t* r, uint32_t addr) {
    asm volatile("ldmatrix.sync.aligned.m8n8.x4.shared.b16 {%0,%1,%2,%3}, [%4];"
                 : "=r"(r[0]), "=r"(r[1]), "=r"(r[2]), "=r"(r[3]) : "r"(addr));
}

__device__ __forceinline__ void ldsm_x2(uint32_t* r, uint32_t addr) {
    asm volatile("ldmatrix.sync.aligned.m8n8.x2.shared.b16 {%0,%1}, [%2];"
                 : "=r"(r[0]), "=r"(r[1]) : "r"(addr));
}

// ---------------------------------------------------------------------------
// Degrees: single E pass, both atomics
// ---------------------------------------------------------------------------
__global__ void deg_kernel(const int* __restrict__ src, const int* __restrict__ dst,
                           float* __restrict__ dout, int* __restrict__ indeg, int E) {
    int i = blockIdx.x * blockDim.x + threadIdx.x;
    if (i < E) {
        atomicAdd(&dout[src[i]], 1.0f);
        atomicAdd(&indeg[dst[i]], 1);
    }
}

__global__ void rsqrt_kernel(float* __restrict__ dout, const int* __restrict__ indeg,
                             float* __restrict__ rsin, int N) {
    int i = blockIdx.x * blockDim.x + threadIdx.x;
    if (i < N) {
        dout[i] = rsqrtf(fmaxf(dout[i], 1.0f));
        rsin[i] = rsqrtf(fmaxf((float)indeg[i], 1.0f));
    }
}

// ---------------------------------------------------------------------------
// Exclusive scan over in-degrees
// ---------------------------------------------------------------------------
__global__ void scan_block(const int* __restrict__ deg, int* __restrict__ excl,
                           int* __restrict__ bsum, int N) {
    __shared__ int ts[256];
    int tid = threadIdx.x;
    int base = blockIdx.x * 1024 + tid * 4;
    int v[4];
    int sum = 0;
#pragma unroll
    for (int i = 0; i < 4; i++) {
        int idx = base + i;
        v[i] = (idx < N) ? deg[idx] : 0;
        sum += v[i];
    }
    ts[tid] = sum;
    __syncthreads();
    for (int off = 1; off < 256; off <<= 1) {
        int t = (tid >= off) ? ts[tid - off] : 0;
        __syncthreads();
        ts[tid] += t;
        __syncthreads();
    }
    if (tid == 255) bsum[blockIdx.x] = ts[255];
    int run = ts[tid] - sum;
#pragma unroll
    for (int i = 0; i < 4; i++) {
        int idx = base + i;
        if (idx < N) excl[idx] = run;
        run += v[i];
    }
}

__global__ void scan_bsum(int* __restrict__ bsum, int nb) {
    __shared__ int s[512];
    int tid = threadIdx.x;
    int v = (tid < nb) ? bsum[tid] : 0;
    s[tid] = v;
    __syncthreads();
    for (int off = 1; off < 512; off <<= 1) {
        int t = (tid >= off) ? s[tid - off] : 0;
        __syncthreads();
        s[tid] += t;
        __syncthreads();
    }
    if (tid < nb) bsum[tid] = s[tid] - v;
}

__global__ void scan_add(const int* __restrict__ excl, const int* __restrict__ bsum,
                         int* __restrict__ row_start, int* __restrict__ cursor,
                         int N, int E) {
    int i = blockIdx.x * blockDim.x + threadIdx.x;
    if (i < N) {
        int v = excl[i] + bsum[i >> 10];
        row_start[i] = v;
        cursor[i] = v;
    }
    if (i == 0) row_start[N] = E;
}

__global__ void fill_csr(const int* __restrict__ src, const int* __restrict__ dst,
                         int* __restrict__ cursor, int* __restrict__ csr_src, int E) {
    int e = blockIdx.x * blockDim.x + threadIdx.x;
    if (e < E) {
        int pos = atomicAdd(&cursor[dst[e]], 1);
        csr_src[pos] = src[e];
    }
}

// ---------------------------------------------------------------------------
// All three W transposes+fp16 conversions in one launch
// ---------------------------------------------------------------------------
__global__ void split_w_all(const float* __restrict__ W0, const float* __restrict__ W1,
                            const float* __restrict__ W2, uint32_t* __restrict__ o0,
                            uint32_t* __restrict__ o1, uint32_t* __restrict__ o2) {
    int idx = blockIdx.x * blockDim.x + threadIdx.x;
    if (idx < 8192) {
        const int KP = 64, BN = 128;
        int n = idx / KP, j = idx % KP;
        o0[idx] = h2bits(__floats2half2_rn(W0[(size_t)(2 * j) * BN + n],
                                           W0[(size_t)(2 * j + 1) * BN + n]));
    } else if (idx < 12288) {
        int i = idx - 8192;
        const int KP = 64, BN = 64;
        int n = i / KP, j = i % KP;
        o1[i] = h2bits(__floats2half2_rn(W1[(size_t)(2 * j) * BN + n],
                                         W1[(size_t)(2 * j + 1) * BN + n]));
    } else if (idx < 14336) {
        int i = idx - 12288;
        const int KP = 32, BN = 64;
        int n = i / KP, j = i % KP;
        o2[i] = h2bits(__floats2half2_rn(W2[(size_t)(2 * j) * BN + n],
                                         W2[(size_t)(2 * j + 1) * BN + n]));
    }
}

// ---------------------------------------------------------------------------
// Layer-0 GEMM (fp32 A, fused rs_out scale) — identical to R12's proven kernel
// ---------------------------------------------------------------------------
template<int K, int BN>
__global__ __launch_bounds__(256, 2)
void gemm_mma(const float* __restrict__ A, const uint32_t* __restrict__ Bt,
              const float* __restrict__ rs_out,
              __half* __restrict__ outh, int nrows)
{
    constexpr int WARPS_M = (BN == 128) ? 2 : 4;
    constexpr int WM = 128 / WARPS_M;
    constexpr int WN = 32;
    constexpr int MF = WM / 16;
    constexpr int NF = 4;
    constexpr int KP = K / 2;
    constexpr int AS32 = 20;
    constexpr int APLANE = 128 * AS32;
    constexpr int BS32 = KP + 4;
    constexpr int NCHUNK = K / 32;

    extern __shared__ __align__(16) uint32_t smw[];
    uint32_t* Bs = smw + 4 * APLANE;

    const int tid = threadIdx.x;
    const int wid = tid >> 5;
    const int lane = tid & 31;
    const int wm = wid % WARPS_M;
    const int wn = wid / WARPS_M;
    const int rowBase = blockIdx.x * 128;
    const int g = lane >> 2;
    const int t4 = lane & 3;

    constexpr int BU4 = BN * KP / 4;
#pragma unroll 4
    for (int idx = tid; idx < BU4; idx += 256) {
        int lin = idx * 4;
        int n = lin / KP;
        int j = lin % KP;
        uint4 v = *(const uint4*)(Bt + (size_t)n * KP + j);
        *(uint4*)(Bs + n * BS32 + j) = v;
    }

    const int a_r = tid >> 1;
    const int a_kh = tid & 1;
    float4 q[4];

    auto load_a = [&](int c) {
        int row = rowBase + a_r;
        int kb = c * 32 + a_kh * 16;
        if (row < nrows) {
            const float* ap = A + (size_t)row * K + kb;
#pragma unroll
            for (int i = 0; i < 4; i++) q[i] = *(const float4*)(ap + i * 4);
            float ro = rs_out[row];
#pragma unroll
            for (int i = 0; i < 4; i++) {
                q[i].x *= ro; q[i].y *= ro; q[i].z *= ro; q[i].w *= ro;
            }
        } else {
#pragma unroll
            for (int i = 0; i < 4; i++) q[i] = make_float4(0.f, 0.f, 0.f, 0.f);
        }
    };
    auto sts_a = [&](int parity) {
        uint32_t* H = smw + parity * 2 * APLANE;
        uint32_t* L = H + APLANE;
#pragma unroll
        for (int h = 0; h < 2; h++) {
            uint2 e0 = split2(q[2 * h].x,     q[2 * h].y);
            uint2 e1 = split2(q[2 * h].z,     q[2 * h].w);
            uint2 e2 = split2(q[2 * h + 1].x, q[2 * h + 1].y);
            uint2 e3 = split2(q[2 * h + 1].z, q[2 * h + 1].w);
            int off = a_r * AS32 + a_kh * 8 + h * 4;
            *(uint4*)(H + off) = make_uint4(e0.x, e1.x, e2.x, e3.x);
            *(uint4*)(L + off) = make_uint4(e0.y, e1.y, e2.y, e3.y);
        }
    };

    const uint32_t smw_base = cvta_smem(smw);
    const uint32_t a_lane_off = (uint32_t)(lane & 15) * (AS32 * 4) + ((lane >> 4) << 4);
    const uint32_t b_base = cvta_smem(Bs);
    const uint32_t b_lane_off = (uint32_t)(lane & 7) * (BS32 * 4) + (((lane >> 3) & 1) << 4);

    load_a(0);
    sts_a(0);
    __syncthreads();

    float acc[MF][NF][4];
#pragma unroll
    for (int i = 0; i < MF; i++)
#pragma unroll
        for (int j = 0; j < NF; j++)
#pragma unroll
            for (int c = 0; c < 4; c++) acc[i][j][c] = 0.f;

#pragma unroll
    for (int c = 0; c < NCHUNK; c++) {
        const uint32_t ahi_base = smw_base + (uint32_t)(c & 1) * (2 * APLANE * 4);
        const uint32_t alo_base = ahi_base + APLANE * 4;
        if (c + 1 < NCHUNK) load_a(c + 1);

#pragma unroll
        for (int ks = 0; ks < 2; ks++) {
            const uint32_t akoff = (uint32_t)(ks * 16) * 2;
            uint32_t ah[MF][4], al[MF][4];
#pragma unroll
            for (int mf = 0; mf < MF; mf++) {
                uint32_t rowoff = (uint32_t)(wm * WM + mf * 16) * (AS32 * 4);
                ldsm_x4(ah[mf], ahi_base + rowoff + akoff + a_lane_off);
                ldsm_x4(al[mf], alo_base + rowoff + akoff + a_lane_off);
            }
            uint32_t bh[NF][2];
            const uint32_t bkoff = (uint32_t)(c * 32 + ks * 16) * 2;
#pragma unroll
            for (int nf = 0; nf < NF; nf++) {
                uint32_t noff = (uint32_t)(wn * WN + nf * 8) * (BS32 * 4);
                ldsm_x2(bh[nf], b_base + noff + bkoff + b_lane_off);
            }
#pragma unroll
            for (int mf = 0; mf < MF; mf++)
#pragma unroll
                for (int nf = 0; nf < NF; nf++) {
                    mma_f16(acc[mf][nf], ah[mf], bh[nf]);
                    mma_f16(acc[mf][nf], al[mf], bh[nf]);
                }
        }
        if (c + 1 < NCHUNK) {
            sts_a((c + 1) & 1);
            __syncthreads();
        }
    }

#pragma unroll
    for (int mf = 0; mf < MF; mf++) {
#pragma unroll
        for (int nf = 0; nf < NF; nf++) {
            int r0 = rowBase + wm * WM + mf * 16 + g;
            int col = wn * WN + nf * 8 + t4 * 2;
            if (r0 < nrows)
                *(__half2*)(outh + (size_t)r0 * BN + col) =
                    __floats2half2_rn(acc[mf][nf][0], acc[mf][nf][1]);
            if (r0 + 8 < nrows)
                *(__half2*)(outh + (size_t)(r0 + 8) * BN + col) =
                    __floats2half2_rn(acc[mf][nf][2], acc[mf][nf][3]);
        }
    }
}

// ---------------------------------------------------------------------------
// Layers 1-2 GEMM: A already pre-split as uint2(hi2,lo2) pairs [N][K/2].
// Pure-copy A path, fully typed pointers.
// ---------------------------------------------------------------------------
template<int K, int BN>
__global__ __launch_bounds__(256, 2)
void gemm_mma_pre(const uint2* __restrict__ Ap, const uint32_t* __restrict__ Bt,
                  __half* __restrict__ outh, int nrows)
{
    constexpr int WARPS_M = (BN == 128) ? 2 : 4;
    constexpr int WM = 128 / WARPS_M;
    constexpr int WN = 32;
    constexpr int MF = WM / 16;
    constexpr int NF = 4;
    constexpr int KP = K / 2;
    constexpr int AS32 = 20;
    constexpr int APLANE = 128 * AS32;
    constexpr int BS32 = KP + 4;
    constexpr int NCHUNK = K / 32;

    extern __shared__ __align__(16) uint32_t smw[];
    uint32_t* Bs = smw + 4 * APLANE;

    const int tid = threadIdx.x;
    const int wid = tid >> 5;
    const int lane = tid & 31;
    const int wm = wid % WARPS_M;
    const int wn = wid / WARPS_M;
    const int rowBase = blockIdx.x * 128;
    const int g = lane >> 2;
    const int t4 = lane & 3;

    constexpr int BU4 = BN * KP / 4;
#pragma unroll 4
    for (int idx = tid; idx < BU4; idx += 256) {
        int lin = idx * 4;
        int n = lin / KP;
        int j = lin % KP;
        uint4 v = *(const uint4*)(Bt + (size_t)n * KP + j);
        *(uint4*)(Bs + n * BS32 + j) = v;
    }

    const int a_r = tid >> 1;
    const int a_kh = tid & 1;
    uint4 qp[4];  // 8 uint2 pairs = 16 k values

    auto load_a = [&](int c) {
        int row = rowBase + a_r;
        if (row < nrows) {
            const uint2* ap = Ap + (size_t)row * KP + c * 16 + a_kh * 8;
#pragma unroll
            for (int i = 0; i < 4; i++) qp[i] = *(const uint4*)(ap + i * 2);
        } else {
#pragma unroll
            for (int i = 0; i < 4; i++) qp[i] = make_uint4(0u, 0u, 0u, 0u);
        }
    };
    auto sts_a = [&](int parity) {
        uint32_t* H = smw + parity * 2 * APLANE;
        uint32_t* L = H + APLANE;
#pragma unroll
        for (int h = 0; h < 2; h++) {
            uint4 p0 = qp[2 * h];      // (hi0, lo0, hi1, lo1)
            uint4 p1 = qp[2 * h + 1];  // (hi2, lo2, hi3, lo3)
            int off = a_r * AS32 + a_kh * 8 + h * 4;
            *(uint4*)(H + off) = make_uint4(p0.x, p0.z, p1.x, p1.z);
            *(uint4*)(L + off) = make_uint4(p0.y, p0.w, p1.y, p1.w);
        }
    };

    const uint32_t smw_base = cvta_smem(smw);
    const uint32_t a_lane_off = (uint32_t)(lane & 15) * (AS32 * 4) + ((lane >> 4) << 4);
    const uint32_t b_base = cvta_smem(Bs);
    const uint32_t b_lane_off = (uint32_t)(lane & 7) * (BS32 * 4) + (((lane >> 3) & 1) << 4);

    load_a(0);
    sts_a(0);
    __syncthreads();

    float acc[MF][NF][4];
#pragma unroll
    for (int i = 0; i < MF; i++)
#pragma unroll
        for (int j = 0; j < NF; j++)
#pragma unroll
            for (int c = 0; c < 4; c++) acc[i][j][c] = 0.f;

#pragma unroll
    for (int c = 0; c < NCHUNK; c++) {
        const uint32_t ahi_base = smw_base + (uint32_t)(c & 1) * (2 * APLANE * 4);
        const uint32_t alo_base = ahi_base + APLANE * 4;
        if (c + 1 < NCHUNK) load_a(c + 1);

#pragma unroll
        for (int ks = 0; ks < 2; ks++) {
            const uint32_t akoff = (uint32_t)(ks * 16) * 2;
            uint32_t ah[MF][4], al[MF][4];
#pragma unroll
            for (int mf = 0; mf < MF; mf++) {
                uint32_t rowoff = (uint32_t)(wm * WM + mf * 16) * (AS32 * 4);
                ldsm_x4(ah[mf], ahi_base + rowoff + akoff + a_lane_off);
                ldsm_x4(al[mf], alo_base + rowoff + akoff + a_lane_off);
            }
            uint32_t bh[NF][2];
            const uint32_t bkoff = (uint32_t)(c * 32 + ks * 16) * 2;
#pragma unroll
            for (int nf = 0; nf < NF; nf++) {
                uint32_t noff = (uint32_t)(wn * WN + nf * 8) * (BS32 * 4);
                ldsm_x2(bh[nf], b_base + noff + bkoff + b_lane_off);
            }
#pragma unroll
            for (int mf = 0; mf < MF; mf++)
#pragma unroll
                for (int nf = 0; nf < NF; nf++) {
                    mma_f16(acc[mf][nf], ah[mf], bh[nf]);
                    mma_f16(acc[mf][nf], al[mf], bh[nf]);
                }
        }
        if (c + 1 < NCHUNK) {
            sts_a((c + 1) & 1);
            __syncthreads();
        }
    }

#pragma unroll
    for (int mf = 0; mf < MF; mf++) {
#pragma unroll
        for (int nf = 0; nf < NF; nf++) {
            int r0 = rowBase + wm * WM + mf * 16 + g;
            int col = wn * WN + nf * 8 + t4 * 2;
            if (r0 < nrows)
                *(__half2*)(outh + (size_t)r0 * BN + col) =
                    __floats2half2_rn(acc[mf][nf][0], acc[mf][nf][1]);
            if (r0 + 8 < nrows)
                *(__half2*)(outh + (size_t)(r0 + 8) * BN + col) =
                    __floats2half2_rn(acc[mf][nf][2], acc[mf][nf][3]);
        }
    }
}

// ---------------------------------------------------------------------------
// Fused gathers: aggregate fp16 h, apply next-layer A-epilogue, emit pre-split
// uint2(hi2,lo2) pairs. Same byte volume as the old fp32 agg writes.
// ---------------------------------------------------------------------------
__global__ __launch_bounds__(256)
void gather128_pre(const int* __restrict__ row_start, const int* __restrict__ csr,
                   const __half* __restrict__ h, const float* __restrict__ rs_in,
                   const float* __restrict__ rs_out, const float* __restrict__ b,
                   uint2* __restrict__ apre, int N)
{
    int warp = (blockIdx.x * blockDim.x + threadIdx.x) >> 5;
    int lane = threadIdx.x & 31;
    if (warp >= N) return;
    int start = row_start[warp];
    int end   = row_start[warp + 1];
    float4 acc = make_float4(0.f, 0.f, 0.f, 0.f);
    for (int j = start; j < end; j++) {
        int s0 = __ldg(&csr[j]);
        uint2 raw = *(const uint2*)(h + (size_t)s0 * 128 + lane * 4);
        float2 fa = __half22float2(*(__half2*)&raw.x);
        float2 fb = __half22float2(*(__half2*)&raw.y);
        acc.x += fa.x; acc.y += fa.y; acc.z += fb.x; acc.w += fb.y;
    }
    float ri = rs_in[warp];
    float ro = rs_out[warp];
    int c = lane * 4;
    float x0 = lrelu(fmaf(acc.x, ri, b[c + 0])) * ro;
    float x1 = lrelu(fmaf(acc.y, ri, b[c + 1])) * ro;
    float x2 = lrelu(fmaf(acc.z, ri, b[c + 2])) * ro;
    float x3 = lrelu(fmaf(acc.w, ri, b[c + 3])) * ro;
    uint2 e0 = split2(x0, x1);
    uint2 e1 = split2(x2, x3);
    *(uint4*)(apre + (size_t)warp * 64 + lane * 2) = make_uint4(e0.x, e0.y, e1.x, e1.y);
}

__global__ __launch_bounds__(256)
void gather64_pre(const int* __restrict__ row_start, const int* __restrict__ csr,
                  const __half* __restrict__ h, const float* __restrict__ rs_in,
                  const float* __restrict__ rs_out, const float* __restrict__ b,
                  uint2* __restrict__ apre, int N)
{
    int warp = (blockIdx.x * blockDim.x + threadIdx.x) >> 5;
    int lane = threadIdx.x & 31;
    if (warp >= N) return;
    int start = row_start[warp];
    int end   = row_start[warp + 1];
    float2 acc = make_float2(0.f, 0.f);
    for (int j = start; j < end; j++) {
        int s0 = __ldg(&csr[j]);
        __half2 raw = *(const __half2*)(h + (size_t)s0 * 64 + lane * 2);
        float2 f = __half22float2(raw);
        acc.x += f.x; acc.y += f.y;
    }
    float ri = rs_in[warp];
    float ro = rs_out[warp];
    int c = lane * 2;
    float x0 = lrelu(fmaf(acc.x, ri, b[c + 0])) * ro;
    float x1 = lrelu(fmaf(acc.y, ri, b[c + 1])) * ro;
    apre[(size_t)warp * 32 + lane] = split2(x0, x1);
}

// Final-layer gather with fused epilogue: out = lrelu(acc * rs_in + b2)
__global__ __launch_bounds__(256)
void gather64_epi(const int* __restrict__ row_start, const int* __restrict__ csr,
                  const __half* __restrict__ h, const float* __restrict__ rs_in,
                  const float* __restrict__ b, float* __restrict__ out, int N)
{
    int warp = (blockIdx.x * blockDim.x + threadIdx.x) >> 5;
    int lane = threadIdx.x & 31;
    if (warp >= N) return;
    int start = row_start[warp];
    int end   = row_start[warp + 1];
    float2 acc = make_float2(0.f, 0.f);
    for (int j = start; j < end; j++) {
        int s0 = __ldg(&csr[j]);
        __half2 raw = *(const __half2*)(h + (size_t)s0 * 64 + lane * 2);
        float2 f = __half22float2(raw);
        acc.x += f.x; acc.y += f.y;
    }
    float ri = rs_in[warp];
    int c = lane * 2;
    float2 o;
    o.x = lrelu(fmaf(acc.x, ri, b[c + 0]));
    o.y = lrelu(fmaf(acc.y, ri, b[c + 1]));
    *(float2*)(out + (size_t)warp * 64 + c) = o;
}

// ---------------------------------------------------------------------------
// Launch (serial R12 structure; only change: pre-split handoff)
// ---------------------------------------------------------------------------
static inline int cdiv(int a, int b) { return (a + b - 1) / b; }

extern "C" void kernel_launch(void* const* d_in, const int* in_sizes, int n_in,
                              void* d_out, int out_size)
{
    const float* n_feat = (const float*)d_in[0];
    const int*   src    = (const int*)  d_in[1];
    const int*   dst    = (const int*)  d_in[2];
    const float* W0     = (const float*)d_in[3];
    const float* b0     = (const float*)d_in[4];
    const float* W1     = (const float*)d_in[5];
    const float* b1     = (const float*)d_in[6];
    const float* W2     = (const float*)d_in[7];
    const float* b2     = (const float*)d_in[8];
    float* out = (float*)d_out;

    const int N = in_sizes[0] / 128;
    const int E = in_sizes[1];

    float *d_agg, *d_rso, *d_rsi;
    __half* d_h;
    int *d_indeg, *d_excl, *d_rs, *d_cur, *d_csr, *d_bsum;
    uint32_t *d_bth0, *d_bth1, *d_bth2;
    cudaGetSymbolAddress((void**)&d_h,    g_h16);
    cudaGetSymbolAddress((void**)&d_agg,  g_agg);
    cudaGetSymbolAddress((void**)&d_rso,  g_rs_out);
    cudaGetSymbolAddress((void**)&d_rsi,  g_rs_in);
    cudaGetSymbolAddress((void**)&d_indeg, g_indeg);
    cudaGetSymbolAddress((void**)&d_excl, g_excl);
    cudaGetSymbolAddress((void**)&d_rs,   g_row_start);
    cudaGetSymbolAddress((void**)&d_cur,  g_cursor);
    cudaGetSymbolAddress((void**)&d_csr,  g_csr_src);
    cudaGetSymbolAddress((void**)&d_bsum, g_bsum);
    cudaGetSymbolAddress((void**)&d_bth0, g_bth0);
    cudaGetSymbolAddress((void**)&d_bth1, g_bth1);
    cudaGetSymbolAddress((void**)&d_bth2, g_bth2);
    uint2* d_apre = (uint2*)d_agg;

    constexpr int SMEM_L0 = 4 * 128 * 20 * 4 + 128 * 68 * 4;  // 75776
    constexpr int SMEM_L1 = 4 * 128 * 20 * 4 + 64 * 68 * 4;   // 58368
    constexpr int SMEM_L2 = 4 * 128 * 20 * 4 + 64 * 36 * 4;   // 50176

    static cudaStream_t s2 = nullptr;
    static cudaEvent_t ev0 = nullptr, ev1 = nullptr;
    if (!s2) {
        cudaFuncSetAttribute(gemm_mma<128, 128>,
                             cudaFuncAttributeMaxDynamicSharedMemorySize, SMEM_L0);
        cudaFuncSetAttribute(gemm_mma_pre<128, 64>,
                             cudaFuncAttributeMaxDynamicSharedMemorySize, SMEM_L1);
        cudaFuncSetAttribute(gemm_mma_pre<64, 64>,
                             cudaFuncAttributeMaxDynamicSharedMemorySize, SMEM_L2);
        cudaStreamCreateWithFlags(&s2, cudaStreamNonBlocking);
        cudaEventCreateWithFlags(&ev0, cudaEventDisableTiming);
        cudaEventCreateWithFlags(&ev1, cudaEventDisableTiming);
    }

    const int gemm_blocks = cdiv(N, 128);
    const int gw_blocks = cdiv(N, 8);
    const int nb = cdiv(N, 1024);

    // ---- main stream head (launches 1-6; #6 = gemm0 for ncu -s 5) ----
    cudaMemsetAsync(d_indeg, 0, (size_t)N * sizeof(int));                      // 1
    cudaMemsetAsync(d_rso, 0, (size_t)N * sizeof(float));                      // 2
    deg_kernel<<<cdiv(E, 256), 256>>>(src, dst, d_rso, d_indeg, E);            // 3
    cudaEventRecord(ev0, 0);  // fork point: indeg ready
    rsqrt_kernel<<<cdiv(N, 256), 256>>>(d_rso, d_indeg, d_rsi, N);             // 4
    split_w_all<<<cdiv(14336, 256), 256>>>(W0, W1, W2, d_bth0, d_bth1, d_bth2);// 5
    gemm_mma<128, 128><<<gemm_blocks, 256, SMEM_L0>>>(                         // 6
        n_feat, d_bth0, d_rso, d_h, N);

    // ---- s2: CSR chain, concurrent with rsqrt/split_w/gemm0 ----
    cudaStreamWaitEvent(s2, ev0, 0);
    scan_block<<<nb, 256, 0, s2>>>(d_indeg, d_excl, d_bsum, N);
    scan_bsum<<<1, 512, 0, s2>>>(d_bsum, nb);
    scan_add<<<cdiv(N, 256), 256, 0, s2>>>(d_excl, d_bsum, d_rs, d_cur, N, E);
    fill_csr<<<cdiv(E, 256), 256, 0, s2>>>(src, dst, d_cur, d_csr, E);
    cudaEventRecord(ev1, s2);

    // ---- join: gathers need the CSR ----
    cudaStreamWaitEvent(0, ev1, 0);

    // layer-0 gather fused with layer-1 A-epilogue (pre-split output)
    gather128_pre<<<gw_blocks, 256>>>(d_rs, d_csr, d_h, d_rsi, d_rso, b0, d_apre, N);

    // --- layer 1: 128 -> 64 (pure-copy A path, typed) ---
    gemm_mma_pre<128, 64><<<gemm_blocks, 256, SMEM_L1>>>(d_apre, d_bth1, d_h, N);
    gather64_pre<<<gw_blocks, 256>>>(d_rs, d_csr, d_h, d_rsi, d_rso, b1, d_apre, N);

    // --- layer 2: 64 -> 64 (pure-copy A path, typed) ---
    gemm_mma_pre<64, 64><<<gemm_blocks, 256, SMEM_L2>>>(d_apre, d_bth2, d_h, N);
    gather64_epi<<<gw_blocks, 256>>>(d_rs, d_csr, d_h, d_rsi, b2, out, N);
}

// round 16
// speedup vs baseline: 1.1301x; 1.0234x over previous
#include <cuda_runtime.h>
#include <cuda_bf16.h>
#include <cuda_fp16.h>
#include <cstdint>

#define LEAKY 0.01f

static constexpr int MAX_N = 100000;
static constexpr int MAX_E = 1600000;

// Scratch (module-scope device globals; allocation inside kernel_launch is forbidden)
__device__ __half   g_h16[(size_t)MAX_N * 128];  // GEMM output (fp16) / gather source
__device__ float    g_agg[(size_t)MAX_N * 128];  // gather output (pre-split uint2 view)
__device__ float    g_rs_out[MAX_N];             // rsqrt(max(out_deg,1))
__device__ float    g_rs_in[MAX_N];              // rsqrt(max(in_deg,1))
__device__ int      g_indeg[MAX_N];              // int in-degree counts
__device__ int      g_excl[MAX_N];               // scan scratch
__device__ int      g_row_start[MAX_N + 1];      // CSR row offsets (by dst)
__device__ int      g_cursor[MAX_N];             // CSR fill cursors
__device__ int      g_csr_src[MAX_E];            // CSR column (src node) array
__device__ int      g_bsum[512];                 // scan block sums
__device__ uint32_t g_bth0[128 * 64];            // W0^T fp16-hi half2 [n][k/2]
__device__ uint32_t g_bth1[64 * 64];             // W1^T
__device__ uint32_t g_bth2[64 * 32];             // W2^T

__device__ __forceinline__ float lrelu(float t) {
    return (t >= 0.f) ? t : LEAKY * t;
}

__device__ __forceinline__ uint32_t h2bits(__half2 h) {
    return *reinterpret_cast<uint32_t*>(&h);
}

// split two floats into fp16 hi/lo planes packed as half2 words
__device__ __forceinline__ uint2 split2(float a, float b) {
    __half2 h = __floats2half2_rn(a, b);
    float la = a - __low2float(h);
    float lb = b - __high2float(h);
    __half2 l = __floats2half2_rn(la, lb);
    return make_uint2(h2bits(h), h2bits(l));
}

__device__ __forceinline__ void mma_f16(float* d, const uint32_t* a, const uint32_t* b) {
    asm volatile(
        "mma.sync.aligned.m16n8k16.row.col.f32.f16.f16.f32 "
        "{%0,%1,%2,%3}, {%4,%5,%6,%7}, {%8,%9}, {%0,%1,%2,%3};"
        : "+f"(d[0]), "+f"(d[1]), "+f"(d[2]), "+f"(d[3])
        : "r"(a[0]), "r"(a[1]), "r"(a[2]), "r"(a[3]), "r"(b[0]), "r"(b[1]));
}

__device__ __forceinline__ uint32_t cvta_smem(const void* p) {
    uint32_t a;
    asm("{ .reg .u64 t; cvta.to.shared.u64 t, %1; cvt.u32.u64 %0, t; }" : "=r"(a) : "l"(p));
    return a;
}

__device__ __forceinline__ void ldsm_x4(uint32_t* r, uint32_t addr) {
    asm volatile("ldmatrix.sync.aligned.m8n8.x4.shared.b16 {%0,%1,%2,%3}, [%4];"
                 : "=r"(r[0]), "=r"(r[1]), "=r"(r[2]), "=r"(r[3]) : "r"(addr));
}

__device__ __forceinline__ void ldsm_x2(uint32_t* r, uint32_t addr) {
    asm volatile("ldmatrix.sync.aligned.m8n8.x2.shared.b16 {%0,%1}, [%2];"
                 : "=r"(r[0]), "=r"(r[1]) : "r"(addr));
}

// ---------------------------------------------------------------------------
// Degrees: single E pass, both atomics
// ---------------------------------------------------------------------------
__global__ void deg_kernel(const int* __restrict__ src, const int* __restrict__ dst,
                           float* __restrict__ dout, int* __restrict__ indeg, int E) {
    int i = blockIdx.x * blockDim.x + threadIdx.x;
    if (i < E) {
        atomicAdd(&dout[src[i]], 1.0f);
        atomicAdd(&indeg[dst[i]], 1);
    }
}

__global__ void rsqrt_kernel(float* __restrict__ dout, const int* __restrict__ indeg,
                             float* __restrict__ rsin, int N) {
    int i = blockIdx.x * blockDim.x + threadIdx.x;
    if (i < N) {
        dout[i] = rsqrtf(fmaxf(dout[i], 1.0f));
        rsin[i] = rsqrtf(fmaxf((float)indeg[i], 1.0f));
    }
}

// ---------------------------------------------------------------------------
// Exclusive scan over in-degrees
// ---------------------------------------------------------------------------
__global__ void scan_block(const int* __restrict__ deg, int* __restrict__ excl,
                           int* __restrict__ bsum, int N) {
    __shared__ int ts[256];
    int tid = threadIdx.x;
    int base = blockIdx.x * 1024 + tid * 4;
    int v[4];
    int sum = 0;
#pragma unroll
    for (int i = 0; i < 4; i++) {
        int idx = base + i;
        v[i] = (idx < N) ? deg[idx] : 0;
        sum += v[i];
    }
    ts[tid] = sum;
    __syncthreads();
    for (int off = 1; off < 256; off <<= 1) {
        int t = (tid >= off) ? ts[tid - off] : 0;
        __syncthreads();
        ts[tid] += t;
        __syncthreads();
    }
    if (tid == 255) bsum[blockIdx.x] = ts[255];
    int run = ts[tid] - sum;
#pragma unroll
    for (int i = 0; i < 4; i++) {
        int idx = base + i;
        if (idx < N) excl[idx] = run;
        run += v[i];
    }
}

__global__ void scan_bsum(int* __restrict__ bsum, int nb) {
    __shared__ int s[512];
    int tid = threadIdx.x;
    int v = (tid < nb) ? bsum[tid] : 0;
    s[tid] = v;
    __syncthreads();
    for (int off = 1; off < 512; off <<= 1) {
        int t = (tid >= off) ? s[tid - off] : 0;
        __syncthreads();
        s[tid] += t;
        __syncthreads();
    }
    if (tid < nb) bsum[tid] = s[tid] - v;
}

__global__ void scan_add(const int* __restrict__ excl, const int* __restrict__ bsum,
                         int* __restrict__ row_start, int* __restrict__ cursor,
                         int N, int E) {
    int i = blockIdx.x * blockDim.x + threadIdx.x;
    if (i < N) {
        int v = excl[i] + bsum[i >> 10];
        row_start[i] = v;
        cursor[i] = v;
    }
    if (i == 0) row_start[N] = E;
}

__global__ void fill_csr(const int* __restrict__ src, const int* __restrict__ dst,
                         int* __restrict__ cursor, int* __restrict__ csr_src, int E) {
    int e = blockIdx.x * blockDim.x + threadIdx.x;
    if (e < E) {
        int pos = atomicAdd(&cursor[dst[e]], 1);
        csr_src[pos] = src[e];
    }
}

// ---------------------------------------------------------------------------
// All three W transposes+fp16 conversions in one launch
// ---------------------------------------------------------------------------
__global__ void split_w_all(const float* __restrict__ W0, const float* __restrict__ W1,
                            const float* __restrict__ W2, uint32_t* __restrict__ o0,
                            uint32_t* __restrict__ o1, uint32_t* __restrict__ o2) {
    int idx = blockIdx.x * blockDim.x + threadIdx.x;
    if (idx < 8192) {
        const int KP = 64, BN = 128;
        int n = idx / KP, j = idx % KP;
        o0[idx] = h2bits(__floats2half2_rn(W0[(size_t)(2 * j) * BN + n],
                                           W0[(size_t)(2 * j + 1) * BN + n]));
    } else if (idx < 12288) {
        int i = idx - 8192;
        const int KP = 64, BN = 64;
        int n = i / KP, j = i % KP;
        o1[i] = h2bits(__floats2half2_rn(W1[(size_t)(2 * j) * BN + n],
                                         W1[(size_t)(2 * j + 1) * BN + n]));
    } else if (idx < 14336) {
        int i = idx - 12288;
        const int KP = 32, BN = 64;
        int n = i / KP, j = i % KP;
        o2[i] = h2bits(__floats2half2_rn(W2[(size_t)(2 * j) * BN + n],
                                         W2[(size_t)(2 * j + 1) * BN + n]));
    }
}

// ---------------------------------------------------------------------------
// Layer-0 GEMM, BM=64 tiles for 3 CTAs/SM (fp32 A, fused rs_out scale)
// ---------------------------------------------------------------------------
template<int K, int BN>
__global__ __launch_bounds__(256, 3)
void gemm_mma(const float* __restrict__ A, const uint32_t* __restrict__ Bt,
              const float* __restrict__ rs_out,
              __half* __restrict__ outh, int nrows)
{
    constexpr int WARPS_M = (BN == 128) ? 2 : 4;
    constexpr int WM = 64 / WARPS_M;    // 32 or 16
    constexpr int WN = 32;
    constexpr int MF = WM / 16;         // 2 or 1
    constexpr int NF = 4;
    constexpr int KP = K / 2;
    constexpr int AS32 = 20;            // uint32 per A-plane row
    constexpr int APLANE = 64 * AS32;   // uint32 per plane
    constexpr int BS32 = KP + 4;
    constexpr int NCHUNK = K / 32;

    extern __shared__ __align__(16) uint32_t smw[];
    uint32_t* Bs = smw + 4 * APLANE;

    const int tid = threadIdx.x;
    const int wid = tid >> 5;
    const int lane = tid & 31;
    const int wm = wid % WARPS_M;
    const int wn = wid / WARPS_M;
    const int rowBase = blockIdx.x * 64;
    const int g = lane >> 2;
    const int t4 = lane & 3;

    // ---- load resident B (hi plane only) ----
    constexpr int BU4 = BN * KP / 4;
#pragma unroll 4
    for (int idx = tid; idx < BU4; idx += 256) {
        int lin = idx * 4;
        int n = lin / KP;
        int j = lin % KP;
        uint4 v = *(const uint4*)(Bt + (size_t)n * KP + j);
        *(uint4*)(Bs + n * BS32 + j) = v;
    }

    // ---- A chunk staging: thread covers row (tid>>2), 8 consecutive k ----
    const int a_r = tid >> 2;
    const int a_kq = tid & 3;  // which 8-k slice of the 32-k chunk
    float4 q[2];

    auto load_a = [&](int c) {
        int row = rowBase + a_r;
        int kb = c * 32 + a_kq * 8;
        if (row < nrows) {
            const float* ap = A + (size_t)row * K + kb;
            q[0] = *(const float4*)(ap);
            q[1] = *(const float4*)(ap + 4);
            float ro = rs_out[row];
            q[0].x *= ro; q[0].y *= ro; q[0].z *= ro; q[0].w *= ro;
            q[1].x *= ro; q[1].y *= ro; q[1].z *= ro; q[1].w *= ro;
        } else {
            q[0] = make_float4(0.f, 0.f, 0.f, 0.f);
            q[1] = make_float4(0.f, 0.f, 0.f, 0.f);
        }
    };
    auto sts_a = [&](int parity) {
        uint32_t* H = smw + parity * 2 * APLANE;
        uint32_t* L = H + APLANE;
        uint2 e0 = split2(q[0].x, q[0].y);
        uint2 e1 = split2(q[0].z, q[0].w);
        uint2 e2 = split2(q[1].x, q[1].y);
        uint2 e3 = split2(q[1].z, q[1].w);
        int off = a_r * AS32 + a_kq * 4;
        *(uint4*)(H + off) = make_uint4(e0.x, e1.x, e2.x, e3.x);
        *(uint4*)(L + off) = make_uint4(e0.y, e1.y, e2.y, e3.y);
    };

    const uint32_t smw_base = cvta_smem(smw);
    const uint32_t a_lane_off = (uint32_t)(lane & 15) * (AS32 * 4) + ((lane >> 4) << 4);
    const uint32_t b_base = cvta_smem(Bs);
    const uint32_t b_lane_off = (uint32_t)(lane & 7) * (BS32 * 4) + (((lane >> 3) & 1) << 4);

    load_a(0);
    sts_a(0);
    __syncthreads();

    float acc[MF][NF][4];
#pragma unroll
    for (int i = 0; i < MF; i++)
#pragma unroll
        for (int j = 0; j < NF; j++)
#pragma unroll
            for (int c = 0; c < 4; c++) acc[i][j][c] = 0.f;

#pragma unroll
    for (int c = 0; c < NCHUNK; c++) {
        const uint32_t ahi_base = smw_base + (uint32_t)(c & 1) * (2 * APLANE * 4);
        const uint32_t alo_base = ahi_base + APLANE * 4;
        if (c + 1 < NCHUNK) load_a(c + 1);

#pragma unroll
        for (int ks = 0; ks < 2; ks++) {
            const uint32_t akoff = (uint32_t)(ks * 16) * 2;
            uint32_t ah[MF][4], al[MF][4];
#pragma unroll
            for (int mf = 0; mf < MF; mf++) {
                uint32_t rowoff = (uint32_t)(wm * WM + mf * 16) * (AS32 * 4);
                ldsm_x4(ah[mf], ahi_base + rowoff + akoff + a_lane_off);
                ldsm_x4(al[mf], alo_base + rowoff + akoff + a_lane_off);
            }
            uint32_t bh[NF][2];
            const uint32_t bkoff = (uint32_t)(c * 32 + ks * 16) * 2;
#pragma unroll
            for (int nf = 0; nf < NF; nf++) {
                uint32_t noff = (uint32_t)(wn * WN + nf * 8) * (BS32 * 4);
                ldsm_x2(bh[nf], b_base + noff + bkoff + b_lane_off);
            }
#pragma unroll
            for (int mf = 0; mf < MF; mf++)
#pragma unroll
                for (int nf = 0; nf < NF; nf++) {
                    mma_f16(acc[mf][nf], ah[mf], bh[nf]);
                    mma_f16(acc[mf][nf], al[mf], bh[nf]);
                }
        }
        if (c + 1 < NCHUNK) {
            sts_a((c + 1) & 1);
            __syncthreads();
        }
    }

#pragma unroll
    for (int mf = 0; mf < MF; mf++) {
#pragma unroll
        for (int nf = 0; nf < NF; nf++) {
            int r0 = rowBase + wm * WM + mf * 16 + g;
            int col = wn * WN + nf * 8 + t4 * 2;
            if (r0 < nrows)
                *(__half2*)(outh + (size_t)r0 * BN + col) =
                    __floats2half2_rn(acc[mf][nf][0], acc[mf][nf][1]);
            if (r0 + 8 < nrows)
                *(__half2*)(outh + (size_t)(r0 + 8) * BN + col) =
                    __floats2half2_rn(acc[mf][nf][2], acc[mf][nf][3]);
        }
    }
}

// ---------------------------------------------------------------------------
// Layers 1-2 GEMM, BM=64: A pre-split uint2(hi2,lo2) pairs [N][K/2], pure copy
// ---------------------------------------------------------------------------
template<int K, int BN>
__global__ __launch_bounds__(256, 3)
void gemm_mma_pre(const uint2* __restrict__ Ap, const uint32_t* __restrict__ Bt,
                  __half* __restrict__ outh, int nrows)
{
    constexpr int WARPS_M = (BN == 128) ? 2 : 4;
    constexpr int WM = 64 / WARPS_M;
    constexpr int WN = 32;
    constexpr int MF = WM / 16;
    constexpr int NF = 4;
    constexpr int KP = K / 2;
    constexpr int AS32 = 20;
    constexpr int APLANE = 64 * AS32;
    constexpr int BS32 = KP + 4;
    constexpr int NCHUNK = K / 32;

    extern __shared__ __align__(16) uint32_t smw[];
    uint32_t* Bs = smw + 4 * APLANE;

    const int tid = threadIdx.x;
    const int wid = tid >> 5;
    const int lane = tid & 31;
    const int wm = wid % WARPS_M;
    const int wn = wid / WARPS_M;
    const int rowBase = blockIdx.x * 64;
    const int g = lane >> 2;
    const int t4 = lane & 3;

    constexpr int BU4 = BN * KP / 4;
#pragma unroll 4
    for (int idx = tid; idx < BU4; idx += 256) {
        int lin = idx * 4;
        int n = lin / KP;
        int j = lin % KP;
        uint4 v = *(const uint4*)(Bt + (size_t)n * KP + j);
        *(uint4*)(Bs + n * BS32 + j) = v;
    }

    const int a_r = tid >> 2;
    const int a_kq = tid & 3;  // 4-pair (8-k) slice
    uint4 qp[2];

    auto load_a = [&](int c) {
        int row = rowBase + a_r;
        if (row < nrows) {
            const uint2* ap = Ap + (size_t)row * KP + c * 16 + a_kq * 4;
            qp[0] = *(const uint4*)(ap);
            qp[1] = *(const uint4*)(ap + 2);
        } else {
            qp[0] = make_uint4(0u, 0u, 0u, 0u);
            qp[1] = make_uint4(0u, 0u, 0u, 0u);
        }
    };
    auto sts_a = [&](int parity) {
        uint32_t* H = smw + parity * 2 * APLANE;
        uint32_t* L = H + APLANE;
        int off = a_r * AS32 + a_kq * 4;
        *(uint4*)(H + off) = make_uint4(qp[0].x, qp[0].z, qp[1].x, qp[1].z);
        *(uint4*)(L + off) = make_uint4(qp[0].y, qp[0].w, qp[1].y, qp[1].w);
    };

    const uint32_t smw_base = cvta_smem(smw);
    const uint32_t a_lane_off = (uint32_t)(lane & 15) * (AS32 * 4) + ((lane >> 4) << 4);
    const uint32_t b_base = cvta_smem(Bs);
    const uint32_t b_lane_off = (uint32_t)(lane & 7) * (BS32 * 4) + (((lane >> 3) & 1) << 4);

    load_a(0);
    sts_a(0);
    __syncthreads();

    float acc[MF][NF][4];
#pragma unroll
    for (int i = 0; i < MF; i++)
#pragma unroll
        for (int j = 0; j < NF; j++)
#pragma unroll
            for (int c = 0; c < 4; c++) acc[i][j][c] = 0.f;

#pragma unroll
    for (int c = 0; c < NCHUNK; c++) {
        const uint32_t ahi_base = smw_base + (uint32_t)(c & 1) * (2 * APLANE * 4);
        const uint32_t alo_base = ahi_base + APLANE * 4;
        if (c + 1 < NCHUNK) load_a(c + 1);

#pragma unroll
        for (int ks = 0; ks < 2; ks++) {
            const uint32_t akoff = (uint32_t)(ks * 16) * 2;
            uint32_t ah[MF][4], al[MF][4];
#pragma unroll
            for (int mf = 0; mf < MF; mf++) {
                uint32_t rowoff = (uint32_t)(wm * WM + mf * 16) * (AS32 * 4);
                ldsm_x4(ah[mf], ahi_base + rowoff + akoff + a_lane_off);
                ldsm_x4(al[mf], alo_base + rowoff + akoff + a_lane_off);
            }
            uint32_t bh[NF][2];
            const uint32_t bkoff = (uint32_t)(c * 32 + ks * 16) * 2;
#pragma unroll
            for (int nf = 0; nf < NF; nf++) {
                uint32_t noff = (uint32_t)(wn * WN + nf * 8) * (BS32 * 4);
                ldsm_x2(bh[nf], b_base + noff + bkoff + b_lane_off);
            }
#pragma unroll
            for (int mf = 0; mf < MF; mf++)
#pragma unroll
                for (int nf = 0; nf < NF; nf++) {
                    mma_f16(acc[mf][nf], ah[mf], bh[nf]);
                    mma_f16(acc[mf][nf], al[mf], bh[nf]);
                }
        }
        if (c + 1 < NCHUNK) {
            sts_a((c + 1) & 1);
            __syncthreads();
        }
    }

#pragma unroll
    for (int mf = 0; mf < MF; mf++) {
#pragma unroll
        for (int nf = 0; nf < NF; nf++) {
            int r0 = rowBase + wm * WM + mf * 16 + g;
            int col = wn * WN + nf * 8 + t4 * 2;
            if (r0 < nrows)
                *(__half2*)(outh + (size_t)r0 * BN + col) =
                    __floats2half2_rn(acc[mf][nf][0], acc[mf][nf][1]);
            if (r0 + 8 < nrows)
                *(__half2*)(outh + (size_t)(r0 + 8) * BN + col) =
                    __floats2half2_rn(acc[mf][nf][2], acc[mf][nf][3]);
        }
    }
}

// ---------------------------------------------------------------------------
// Fused gathers: aggregate fp16 h, apply next-layer A-epilogue, emit pre-split
// uint2(hi2,lo2) pairs. Same byte volume as fp32 agg writes.
// ---------------------------------------------------------------------------
__global__ __launch_bounds__(256)
void gather128_pre(const int* __restrict__ row_start, const int* __restrict__ csr,
                   const __half* __restrict__ h, const float* __restrict__ rs_in,
                   const float* __restrict__ rs_out, const float* __restrict__ b,
                   uint2* __restrict__ apre, int N)
{
    int warp = (blockIdx.x * blockDim.x + threadIdx.x) >> 5;
    int lane = threadIdx.x & 31;
    if (warp >= N) return;
    int start = row_start[warp];
    int end   = row_start[warp + 1];
    float4 acc = make_float4(0.f, 0.f, 0.f, 0.f);
    for (int j = start; j < end; j++) {
        int s0 = __ldg(&csr[j]);
        uint2 raw = *(const uint2*)(h + (size_t)s0 * 128 + lane * 4);
        float2 fa = __half22float2(*(__half2*)&raw.x);
        float2 fb = __half22float2(*(__half2*)&raw.y);
        acc.x += fa.x; acc.y += fa.y; acc.z += fb.x; acc.w += fb.y;
    }
    float ri = rs_in[warp];
    float ro = rs_out[warp];
    int c = lane * 4;
    float x0 = lrelu(fmaf(acc.x, ri, b[c + 0])) * ro;
    float x1 = lrelu(fmaf(acc.y, ri, b[c + 1])) * ro;
    float x2 = lrelu(fmaf(acc.z, ri, b[c + 2])) * ro;
    float x3 = lrelu(fmaf(acc.w, ri, b[c + 3])) * ro;
    uint2 e0 = split2(x0, x1);
    uint2 e1 = split2(x2, x3);
    *(uint4*)(apre + (size_t)warp * 64 + lane * 2) = make_uint4(e0.x, e0.y, e1.x, e1.y);
}

__global__ __launch_bounds__(256)
void gather64_pre(const int* __restrict__ row_start, const int* __restrict__ csr,
                  const __half* __restrict__ h, const float* __restrict__ rs_in,
                  const float* __restrict__ rs_out, const float* __restrict__ b,
                  uint2* __restrict__ apre, int N)
{
    int warp = (blockIdx.x * blockDim.x + threadIdx.x) >> 5;
    int lane = threadIdx.x & 31;
    if (warp >= N) return;
    int start = row_start[warp];
    int end   = row_start[warp + 1];
    float2 acc = make_float2(0.f, 0.f);
    for (int j = start; j < end; j++) {
        int s0 = __ldg(&csr[j]);
        __half2 raw = *(const __half2*)(h + (size_t)s0 * 64 + lane * 2);
        float2 f = __half22float2(raw);
        acc.x += f.x; acc.y += f.y;
    }
    float ri = rs_in[warp];
    float ro = rs_out[warp];
    int c = lane * 2;
    float x0 = lrelu(fmaf(acc.x, ri, b[c + 0])) * ro;
    float x1 = lrelu(fmaf(acc.y, ri, b[c + 1])) * ro;
    apre[(size_t)warp * 32 + lane] = split2(x0, x1);
}

// Final-layer gather with fused epilogue: out = lrelu(acc * rs_in + b2)
__global__ __launch_bounds__(256)
void gather64_epi(const int* __restrict__ row_start, const int* __restrict__ csr,
                  const __half* __restrict__ h, const float* __restrict__ rs_in,
                  const float* __restrict__ b, float* __restrict__ out, int N)
{
    int warp = (blockIdx.x * blockDim.x + threadIdx.x) >> 5;
    int lane = threadIdx.x & 31;
    if (warp >= N) return;
    int start = row_start[warp];
    int end   = row_start[warp + 1];
    float2 acc = make_float2(0.f, 0.f);
    for (int j = start; j < end; j++) {
        int s0 = __ldg(&csr[j]);
        __half2 raw = *(const __half2*)(h + (size_t)s0 * 64 + lane * 2);
        float2 f = __half22float2(raw);
        acc.x += f.x; acc.y += f.y;
    }
    float ri = rs_in[warp];
    int c = lane * 2;
    float2 o;
    o.x = lrelu(fmaf(acc.x, ri, b[c + 0]));
    o.y = lrelu(fmaf(acc.y, ri, b[c + 1]));
    *(float2*)(out + (size_t)warp * 64 + c) = o;
}

// ---------------------------------------------------------------------------
// Launch (serial R15 structure; BM=64 GEMM tiles)
// ---------------------------------------------------------------------------
static inline int cdiv(int a, int b) { return (a + b - 1) / b; }

extern "C" void kernel_launch(void* const* d_in, const int* in_sizes, int n_in,
                              void* d_out, int out_size)
{
    const float* n_feat = (const float*)d_in[0];
    const int*   src    = (const int*)  d_in[1];
    const int*   dst    = (const int*)  d_in[2];
    const float* W0     = (const float*)d_in[3];
    const float* b0     = (const float*)d_in[4];
    const float* W1     = (const float*)d_in[5];
    const float* b1     = (const float*)d_in[6];
    const float* W2     = (const float*)d_in[7];
    const float* b2     = (const float*)d_in[8];
    float* out = (float*)d_out;

    const int N = in_sizes[0] / 128;
    const int E = in_sizes[1];

    float *d_agg, *d_rso, *d_rsi;
    __half* d_h;
    int *d_indeg, *d_excl, *d_rs, *d_cur, *d_csr, *d_bsum;
    uint32_t *d_bth0, *d_bth1, *d_bth2;
    cudaGetSymbolAddress((void**)&d_h,    g_h16);
    cudaGetSymbolAddress((void**)&d_agg,  g_agg);
    cudaGetSymbolAddress((void**)&d_rso,  g_rs_out);
    cudaGetSymbolAddress((void**)&d_rsi,  g_rs_in);
    cudaGetSymbolAddress((void**)&d_indeg, g_indeg);
    cudaGetSymbolAddress((void**)&d_excl, g_excl);
    cudaGetSymbolAddress((void**)&d_rs,   g_row_start);
    cudaGetSymbolAddress((void**)&d_cur,  g_cursor);
    cudaGetSymbolAddress((void**)&d_csr,  g_csr_src);
    cudaGetSymbolAddress((void**)&d_bsum, g_bsum);
    cudaGetSymbolAddress((void**)&d_bth0, g_bth0);
    cudaGetSymbolAddress((void**)&d_bth1, g_bth1);
    cudaGetSymbolAddress((void**)&d_bth2, g_bth2);
    uint2* d_apre = (uint2*)d_agg;

    // SMEM: 4 A-planes (2 buf x hi/lo, 64 rows) + B rows
    constexpr int SMEM_L0 = 4 * 64 * 20 * 4 + 128 * 68 * 4;  // 55296
    constexpr int SMEM_L1 = 4 * 64 * 20 * 4 + 64 * 68 * 4;   // 37888
    constexpr int SMEM_L2 = 4 * 64 * 20 * 4 + 64 * 36 * 4;   // 29696

    static cudaStream_t s2 = nullptr;
    static cudaEvent_t ev0 = nullptr, ev1 = nullptr;
    if (!s2) {
        cudaFuncSetAttribute(gemm_mma<128, 128>,
                             cudaFuncAttributeMaxDynamicSharedMemorySize, SMEM_L0);
        cudaFuncSetAttribute(gemm_mma_pre<128, 64>,
                             cudaFuncAttributeMaxDynamicSharedMemorySize, SMEM_L1);
        cudaFuncSetAttribute(gemm_mma_pre<64, 64>,
                             cudaFuncAttributeMaxDynamicSharedMemorySize, SMEM_L2);
        cudaStreamCreateWithFlags(&s2, cudaStreamNonBlocking);
        cudaEventCreateWithFlags(&ev0, cudaEventDisableTiming);
        cudaEventCreateWithFlags(&ev1, cudaEventDisableTiming);
    }

    const int gemm_blocks = cdiv(N, 64);
    const int gw_blocks = cdiv(N, 8);
    const int nb = cdiv(N, 1024);

    // ---- main stream head (launches 1-6; #6 = gemm0 for ncu -s 5) ----
    cudaMemsetAsync(d_indeg, 0, (size_t)N * sizeof(int));                      // 1
    cudaMemsetAsync(d_rso, 0, (size_t)N * sizeof(float));                      // 2
    deg_kernel<<<cdiv(E, 256), 256>>>(src, dst, d_rso, d_indeg, E);            // 3
    cudaEventRecord(ev0, 0);  // fork point: indeg ready
    rsqrt_kernel<<<cdiv(N, 256), 256>>>(d_rso, d_indeg, d_rsi, N);             // 4
    split_w_all<<<cdiv(14336, 256), 256>>>(W0, W1, W2, d_bth0, d_bth1, d_bth2);// 5
    gemm_mma<128, 128><<<gemm_blocks, 256, SMEM_L0>>>(                         // 6
        n_feat, d_bth0, d_rso, d_h, N);

    // ---- s2: CSR chain, concurrent with rsqrt/split_w/gemm0 ----
    cudaStreamWaitEvent(s2, ev0, 0);
    scan_block<<<nb, 256, 0, s2>>>(d_indeg, d_excl, d_bsum, N);
    scan_bsum<<<1, 512, 0, s2>>>(d_bsum, nb);
    scan_add<<<cdiv(N, 256), 256, 0, s2>>>(d_excl, d_bsum, d_rs, d_cur, N, E);
    fill_csr<<<cdiv(E, 256), 256, 0, s2>>>(src, dst, d_cur, d_csr, E);
    cudaEventRecord(ev1, s2);

    // ---- join: gathers need the CSR ----
    cudaStreamWaitEvent(0, ev1, 0);

    // layer-0 gather fused with layer-1 A-epilogue (pre-split output)
    gather128_pre<<<gw_blocks, 256>>>(d_rs, d_csr, d_h, d_rsi, d_rso, b0, d_apre, N);

    // --- layer 1: 128 -> 64 ---
    gemm_mma_pre<128, 64><<<gemm_blocks, 256, SMEM_L1>>>(d_apre, d_bth1, d_h, N);
    gather64_pre<<<gw_blocks, 256>>>(d_rs, d_csr, d_h, d_rsi, d_rso, b1, d_apre, N);

    // --- layer 2: 64 -> 64 ---
    gemm_mma_pre<64, 64><<<gemm_blocks, 256, SMEM_L2>>>(d_apre, d_bth2, d_h, N);
    gather64_epi<<<gw_blocks, 256>>>(d_rs, d_csr, d_h, d_rsi, b2, out, N);
}